// round 1
// baseline (speedup 1.0000x reference)
#include <cuda_runtime.h>
#include <math.h>

#define N 4096
#define D 768
#define TEMP_INV 20.0f   // 1 / 0.05
#define EPSN 1e-8f

// Scratch (allocation-free: device globals)
__device__ float g_logits[(size_t)N * N];   // 64 MB
__device__ float g_inv1[N];
__device__ float g_inv2[N];
__device__ float g_rowloss[N];

// ---------------------------------------------------------------------------
// Kernel 1: per-row inverse L2 norms for both feature matrices.
// grid = (N, 2), block = 256. y==0 -> f1, y==1 -> f2.
// ---------------------------------------------------------------------------
__global__ void k_norms(const float* __restrict__ f1, const float* __restrict__ f2) {
    const int row = blockIdx.x;
    const float* __restrict__ src = (blockIdx.y == 0) ? f1 : f2;
    float* __restrict__ dst = (blockIdx.y == 0) ? g_inv1 : g_inv2;

    const float* p = src + (size_t)row * D;
    float s = 0.0f;
    for (int i = threadIdx.x; i < D; i += 256) {
        float v = p[i];
        s = fmaf(v, v, s);
    }
    __shared__ float sm[256];
    sm[threadIdx.x] = s;
    __syncthreads();
    #pragma unroll
    for (int off = 128; off > 0; off >>= 1) {
        if (threadIdx.x < off) sm[threadIdx.x] += sm[threadIdx.x + off];
        __syncthreads();
    }
    if (threadIdx.x == 0) {
        dst[row] = 1.0f / fmaxf(sqrtf(sm[0]), EPSN);
    }
}

// ---------------------------------------------------------------------------
// Kernel 2: NT SGEMM, C[i][j] = (sum_d A[i][d]*B[j][d]) * inv1[i]*inv2[j]/TEMP
// 128x128 tile per block, BK=8, 256 threads, 8x8 per-thread microtile.
// ---------------------------------------------------------------------------
__global__ __launch_bounds__(256, 2)
void k_gemm(const float* __restrict__ A, const float* __restrict__ B) {
    __shared__ float As[8][128];
    __shared__ float Bs[8][128];

    const int bi = blockIdx.y * 128;
    const int bj = blockIdx.x * 128;
    const int tid = threadIdx.x;

    // loading assignment: 128 rows x 8 cols tile -> 256 float4 loads
    const int lrow = tid >> 1;          // 0..127
    const int lc4  = (tid & 1) * 4;     // 0 or 4

    // compute assignment: 16x16 threads, 8x8 each
    const int ty = tid >> 4;            // 0..15
    const int tx = tid & 15;            // 0..15

    const float* Ap = A + (size_t)(bi + lrow) * D + lc4;
    const float* Bp = B + (size_t)(bj + lrow) * D + lc4;

    float c[8][8];
    #pragma unroll
    for (int i = 0; i < 8; i++)
        #pragma unroll
        for (int j = 0; j < 8; j++)
            c[i][j] = 0.0f;

    for (int k0 = 0; k0 < D; k0 += 8) {
        const float4 a4 = *(const float4*)(Ap + k0);
        const float4 b4 = *(const float4*)(Bp + k0);
        As[lc4 + 0][lrow] = a4.x;
        As[lc4 + 1][lrow] = a4.y;
        As[lc4 + 2][lrow] = a4.z;
        As[lc4 + 3][lrow] = a4.w;
        Bs[lc4 + 0][lrow] = b4.x;
        Bs[lc4 + 1][lrow] = b4.y;
        Bs[lc4 + 2][lrow] = b4.z;
        Bs[lc4 + 3][lrow] = b4.w;
        __syncthreads();

        #pragma unroll
        for (int k = 0; k < 8; k++) {
            float a[8], b[8];
            #pragma unroll
            for (int u = 0; u < 8; u++) {
                a[u] = As[k][ty * 8 + u];
                b[u] = Bs[k][tx * 8 + u];
            }
            #pragma unroll
            for (int i = 0; i < 8; i++)
                #pragma unroll
                for (int j = 0; j < 8; j++)
                    c[i][j] = fmaf(a[i], b[j], c[i][j]);
        }
        __syncthreads();
    }

    // fused scaling + store
    #pragma unroll
    for (int i = 0; i < 8; i++) {
        const int gi = bi + ty * 8 + i;
        const float si = TEMP_INV * g_inv1[gi];
        float* outp = g_logits + (size_t)gi * N + bj + tx * 8;
        #pragma unroll
        for (int j = 0; j < 8; j++) {
            outp[j] = c[i][j] * si * g_inv2[bj + tx * 8 + j];
        }
    }
}

// ---------------------------------------------------------------------------
// Kernel 3: per-row loss_i = -(logit[i,i] - max_i - log(sum_j exp(logit[i,j]-max_i)))
// grid = N blocks, 256 threads.
// ---------------------------------------------------------------------------
__global__ void k_rowloss() {
    const int row = blockIdx.x;
    const float* __restrict__ p = g_logits + (size_t)row * N;
    __shared__ float sm[256];

    // max
    float m = -INFINITY;
    for (int j = threadIdx.x; j < N; j += 256) m = fmaxf(m, p[j]);
    sm[threadIdx.x] = m;
    __syncthreads();
    #pragma unroll
    for (int off = 128; off > 0; off >>= 1) {
        if (threadIdx.x < off) sm[threadIdx.x] = fmaxf(sm[threadIdx.x], sm[threadIdx.x + off]);
        __syncthreads();
    }
    const float mx = sm[0];
    __syncthreads();

    // sum exp
    float s = 0.0f;
    for (int j = threadIdx.x; j < N; j += 256) s += expf(p[j] - mx);
    sm[threadIdx.x] = s;
    __syncthreads();
    #pragma unroll
    for (int off = 128; off > 0; off >>= 1) {
        if (threadIdx.x < off) sm[threadIdx.x] += sm[threadIdx.x + off];
        __syncthreads();
    }
    if (threadIdx.x == 0) {
        g_rowloss[row] = -(p[row] - mx - logf(sm[0]));
    }
}

// ---------------------------------------------------------------------------
// Kernel 4: deterministic mean over the N row losses -> scalar output.
// ---------------------------------------------------------------------------
__global__ void k_finalize(float* __restrict__ out) {
    __shared__ float sm[256];
    float s = 0.0f;
    for (int i = threadIdx.x; i < N; i += 256) s += g_rowloss[i];
    sm[threadIdx.x] = s;
    __syncthreads();
    #pragma unroll
    for (int off = 128; off > 0; off >>= 1) {
        if (threadIdx.x < off) sm[threadIdx.x] += sm[threadIdx.x + off];
        __syncthreads();
    }
    if (threadIdx.x == 0) out[0] = sm[0] / (float)N;
}

// ---------------------------------------------------------------------------
extern "C" void kernel_launch(void* const* d_in, const int* in_sizes, int n_in,
                              void* d_out, int out_size) {
    const float* f1 = (const float*)d_in[0];
    const float* f2 = (const float*)d_in[1];
    float* out = (float*)d_out;

    k_norms<<<dim3(N, 2), 256>>>(f1, f2);
    k_gemm<<<dim3(N / 128, N / 128), 256>>>(f1, f2);
    k_rowloss<<<N, 256>>>();
    k_finalize<<<1, 256>>>(out);
}

// round 3
// speedup vs baseline: 5.9528x; 5.9528x over previous
#include <cuda_runtime.h>
#include <cuda_bf16.h>
#include <math.h>
#include <stdint.h>

#define N 4096
#define D 768
#define TEMP_INV 20.0f
#define EPSN 1e-8f

#define BK 32
#define NCH (D / BK)      // 24 k-chunks
#define STAGE_BYTES 16384 // 8KB A + 8KB B
#define SMEM_DYN (4 * STAGE_BYTES)

// ---------------------------------------------------------------------------
// Scratch (allocation-free: device globals)
// ---------------------------------------------------------------------------
__device__ __nv_bfloat16 g_a[(size_t)N * D];
__device__ __nv_bfloat16 g_b[(size_t)N * D];
__device__ float g_partial[(size_t)N * 32];  // per-row expsum partial per col-block
__device__ float g_diag[N];
__device__ float g_rowloss[N];

// ---------------------------------------------------------------------------
__device__ __forceinline__ uint32_t smem_u32(const void* p) {
    uint32_t a;
    asm("{ .reg .u64 t; cvta.to.shared.u64 t, %1; cvt.u32.u64 %0, t; }" : "=r"(a) : "l"(p));
    return a;
}

#define CP_ASYNC16(dst, src) \
    asm volatile("cp.async.cg.shared.global [%0], [%1], 16;" :: "r"(dst), "l"(src) : "memory")
#define CP_COMMIT() asm volatile("cp.async.commit_group;" ::: "memory")
#define CP_WAIT(n)  asm volatile("cp.async.wait_group %0;" :: "n"(n) : "memory")

__device__ __forceinline__ void ldmx4(uint32_t* r, uint32_t addr) {
    asm volatile("ldmatrix.sync.aligned.m8n8.x4.shared.b16 {%0,%1,%2,%3}, [%4];"
                 : "=r"(r[0]), "=r"(r[1]), "=r"(r[2]), "=r"(r[3]) : "r"(addr));
}

__device__ __forceinline__ void mma_bf16(float* c, const uint32_t* a, const uint32_t* b) {
    asm volatile(
        "mma.sync.aligned.m16n8k16.row.col.f32.bf16.bf16.f32 "
        "{%0,%1,%2,%3}, {%4,%5,%6,%7}, {%8,%9}, {%0,%1,%2,%3};"
        : "+f"(c[0]), "+f"(c[1]), "+f"(c[2]), "+f"(c[3])
        : "r"(a[0]), "r"(a[1]), "r"(a[2]), "r"(a[3]), "r"(b[0]), "r"(b[1]));
}

// ---------------------------------------------------------------------------
// Kernel 1: per-row L2-normalize both matrices, emit bf16.
// ---------------------------------------------------------------------------
__global__ void k_norm_cvt(const float* __restrict__ f1, const float* __restrict__ f2) {
    const int row = blockIdx.x;
    const float* __restrict__ src = (blockIdx.y == 0) ? f1 : f2;
    __nv_bfloat16* __restrict__ dst = (blockIdx.y == 0) ? g_a : g_b;

    const float* p = src + (size_t)row * D;
    float s = 0.0f;
    for (int i = threadIdx.x; i < D; i += 256) {
        float v = p[i];
        s = fmaf(v, v, s);
    }
    __shared__ float sm[256];
    sm[threadIdx.x] = s;
    __syncthreads();
    #pragma unroll
    for (int off = 128; off > 0; off >>= 1) {
        if (threadIdx.x < off) sm[threadIdx.x] += sm[threadIdx.x + off];
        __syncthreads();
    }
    const float inv = 1.0f / fmaxf(sqrtf(sm[0]), EPSN);
    __nv_bfloat16* q = dst + (size_t)row * D;
    for (int i = threadIdx.x; i < D; i += 256) {
        q[i] = __float2bfloat16_rn(p[i] * inv);
    }
}

// ---------------------------------------------------------------------------
// Kernel 2: bf16 mma.sync GEMM with fused exp-sum epilogue.
// CTA: 128x128 tile, 8 warps in 2x4, each warp 64x32 via m16n8k16.
// Smem: 4 stages x (A 128x32 + B 128x32) bf16, chunk-XOR swizzle.
// Writes only g_partial[row][bx] = sum_j exp(logit-20) over this col block,
// and g_diag on diagonal blocks. Logits never hit gmem.
// ---------------------------------------------------------------------------
__global__ __launch_bounds__(256)
void k_gemm_fused() {
    extern __shared__ char smem[];
    const uint32_t sbase = smem_u32(smem);
    const int tid = threadIdx.x;
    const int wid = tid >> 5;
    const int lane = tid & 31;
    const int bx = blockIdx.x, by = blockIdx.y;
    const int bi = by * 128, bj = bx * 128;

    const int wy = wid >> 2;        // 0..1  -> rows
    const int wx = wid & 3;         // 0..3  -> cols
    const int m0 = wy * 64;
    const int n0 = wx * 32;

    // cp.async staging of chunk c (k0 = c*32) into stage s
    auto load_chunk = [&](int c, int s) {
        const int k0 = c * BK;
        const uint32_t st = sbase + s * STAGE_BYTES;
        #pragma unroll
        for (int i = 0; i < 4; i++) {
            const int idx = tid + i * 256;          // 0..1023
            const int isB = idx >> 9;               // 0: A, 1: B
            const int id2 = idx & 511;
            const int row = id2 >> 2;               // 0..127
            const int ch  = id2 & 3;                // 16B chunk in 64B row
            const uint32_t soff = (uint32_t)(row * 64 + ((ch ^ (row & 3)) << 4));
            const __nv_bfloat16* src = (isB ? g_b + (size_t)(bj + row) * D
                                            : g_a + (size_t)(bi + row) * D) + k0 + ch * 8;
            CP_ASYNC16(st + isB * 8192 + soff, src);
        }
    };

    // ldmatrix lane-address precompute
    uint32_t aRB[4], aR3[4];
    #pragma unroll
    for (int mt = 0; mt < 4; mt++) {
        const int r = m0 + mt * 16 + (lane & 15);
        aRB[mt] = (uint32_t)(r * 64);
        aR3[mt] = (uint32_t)(r & 3);
    }
    uint32_t bRB[2], bR3[2];
    #pragma unroll
    for (int p = 0; p < 2; p++) {
        const int r = n0 + p * 16 + ((lane >> 4) << 3) + (lane & 7);
        bRB[p] = (uint32_t)(r * 64);
        bR3[p] = (uint32_t)(r & 3);
    }
    const uint32_t chA = (uint32_t)(lane >> 4);        // 0/1
    const uint32_t chB = (uint32_t)((lane >> 3) & 1);  // 0/1

    float acc[4][4][4];
    #pragma unroll
    for (int mt = 0; mt < 4; mt++)
        #pragma unroll
        for (int nt = 0; nt < 4; nt++)
            #pragma unroll
            for (int r = 0; r < 4; r++) acc[mt][nt][r] = 0.0f;

    // prologue: 3 stages in flight
    load_chunk(0, 0); CP_COMMIT();
    load_chunk(1, 1); CP_COMMIT();
    load_chunk(2, 2); CP_COMMIT();

    for (int c = 0; c < NCH; c++) {
        CP_WAIT(2);
        __syncthreads();
        if (c + 3 < NCH) load_chunk(c + 3, (c + 3) & 3);
        CP_COMMIT();

        const uint32_t sA = sbase + (c & 3) * STAGE_BYTES;
        const uint32_t sB = sA + 8192;

        #pragma unroll
        for (int ks = 0; ks < 2; ks++) {
            uint32_t a[4][4];
            #pragma unroll
            for (int mt = 0; mt < 4; mt++) {
                const uint32_t ch = 2 * ks + chA;
                ldmx4(a[mt], sA + aRB[mt] + ((ch ^ aR3[mt]) << 4));
            }
            uint32_t b[4][2];
            #pragma unroll
            for (int p = 0; p < 2; p++) {
                uint32_t t[4];
                const uint32_t ch = 2 * ks + chB;
                ldmx4(t, sB + bRB[p] + ((ch ^ bR3[p]) << 4));
                b[2 * p][0] = t[0]; b[2 * p][1] = t[1];
                b[2 * p + 1][0] = t[2]; b[2 * p + 1][1] = t[3];
            }
            #pragma unroll
            for (int mt = 0; mt < 4; mt++)
                #pragma unroll
                for (int nt = 0; nt < 4; nt++)
                    mma_bf16(acc[mt][nt], a[mt], b[nt]);
        }
    }

    // ---------------- fused epilogue ----------------
    const int g = lane >> 2;
    const int tig = lane & 3;
    const bool diagBlk = (bx == by);

    float rowsum[8];
    #pragma unroll
    for (int h = 0; h < 8; h++) rowsum[h] = 0.0f;

    #pragma unroll
    for (int mt = 0; mt < 4; mt++) {
        #pragma unroll
        for (int nt = 0; nt < 4; nt++) {
            const float v0 = acc[mt][nt][0] * TEMP_INV;
            const float v1 = acc[mt][nt][1] * TEMP_INV;
            const float v2 = acc[mt][nt][2] * TEMP_INV;
            const float v3 = acc[mt][nt][3] * TEMP_INV;
            rowsum[mt * 2 + 0] += __expf(v0 - 20.0f) + __expf(v1 - 20.0f);
            rowsum[mt * 2 + 1] += __expf(v2 - 20.0f) + __expf(v3 - 20.0f);
            if (diagBlk) {
                const int i0 = m0 + mt * 16 + g;
                const int i1 = i0 + 8;
                const int j0 = n0 + nt * 8 + tig * 2;
                if (i0 == j0)     g_diag[bi + i0] = v0;
                if (i0 == j0 + 1) g_diag[bi + i0] = v1;
                if (i1 == j0)     g_diag[bi + i1] = v2;
                if (i1 == j0 + 1) g_diag[bi + i1] = v3;
            }
        }
    }
    // reduce across the 4 lanes sharing each row (tig group)
    #pragma unroll
    for (int h = 0; h < 8; h++) {
        rowsum[h] += __shfl_xor_sync(0xFFFFFFFFu, rowsum[h], 1);
        rowsum[h] += __shfl_xor_sync(0xFFFFFFFFu, rowsum[h], 2);
    }

    __syncthreads();  // done with smem stages; reuse for partials
    float* part = (float*)smem;  // [128][4]
    if (tig == 0) {
        #pragma unroll
        for (int h = 0; h < 8; h++) {
            const int r = m0 + (h >> 1) * 16 + (h & 1) * 8 + g;
            part[r * 4 + wx] = rowsum[h];
        }
    }
    __syncthreads();
    if (tid < 128) {
        const float s = part[tid * 4 + 0] + part[tid * 4 + 1] +
                        part[tid * 4 + 2] + part[tid * 4 + 3];
        g_partial[(size_t)(bi + tid) * 32 + bx] = s;
    }
}

// ---------------------------------------------------------------------------
// Kernel 3: per-row loss from 32 partials + diag.
// loss_i = log(sum exp(l-20)) + 20 - l_ii
// ---------------------------------------------------------------------------
__global__ void k_rowloss() {
    const int row = blockIdx.x * 128 + threadIdx.x;
    const float4* p = (const float4*)(g_partial + (size_t)row * 32);
    float s = 0.0f;
    #pragma unroll
    for (int i = 0; i < 8; i++) {
        float4 v = p[i];
        s += v.x + v.y + v.z + v.w;
    }
    g_rowloss[row] = logf(s) + 20.0f - g_diag[row];
}

// ---------------------------------------------------------------------------
// Kernel 4: deterministic mean.
// ---------------------------------------------------------------------------
__global__ void k_finalize(float* __restrict__ out) {
    __shared__ float sm[1024];
    float s = 0.0f;
    for (int i = threadIdx.x; i < N; i += 1024) s += g_rowloss[i];
    sm[threadIdx.x] = s;
    __syncthreads();
    #pragma unroll
    for (int off = 512; off > 0; off >>= 1) {
        if (threadIdx.x < off) sm[threadIdx.x] += sm[threadIdx.x + off];
        __syncthreads();
    }
    if (threadIdx.x == 0) out[0] = sm[0] / (float)N;
}

// ---------------------------------------------------------------------------
extern "C" void kernel_launch(void* const* d_in, const int* in_sizes, int n_in,
                              void* d_out, int out_size) {
    const float* f1 = (const float*)d_in[0];
    const float* f2 = (const float*)d_in[1];
    float* out = (float*)d_out;

    cudaFuncSetAttribute(k_gemm_fused, cudaFuncAttributeMaxDynamicSharedMemorySize, SMEM_DYN);

    k_norm_cvt<<<dim3(N, 2), 256>>>(f1, f2);
    k_gemm_fused<<<dim3(N / 128, N / 128), 256, SMEM_DYN>>>();
    k_rowloss<<<N / 128, 128>>>();
    k_finalize<<<1, 1024>>>(out);
}

// round 4
// speedup vs baseline: 9.3053x; 1.5632x over previous
#include <cuda_runtime.h>
#include <cuda_bf16.h>
#include <math.h>
#include <stdint.h>

#define N 4096
#define D 768
#define TEMP_INV 20.0f
#define EPSN 1e-8f

#define BK 64
#define NCH (D / BK)        // 12 k-chunks
#define STAGE_BYTES 32768   // 16KB A + 16KB B
#define SMEM_DYN (3 * STAGE_BYTES)   // 96 KB

// ---------------------------------------------------------------------------
// Scratch (allocation-free: device globals)
// ---------------------------------------------------------------------------
__device__ __nv_bfloat16 g_a[(size_t)N * D];
__device__ __nv_bfloat16 g_b[(size_t)N * D];
__device__ float g_partial[(size_t)N * 32];
__device__ float g_diag[N];
__device__ float g_rowloss[N];
__device__ int   g_done;

// ---------------------------------------------------------------------------
__device__ __forceinline__ uint32_t smem_u32(const void* p) {
    uint32_t a;
    asm("{ .reg .u64 t; cvta.to.shared.u64 t, %1; cvt.u32.u64 %0, t; }" : "=r"(a) : "l"(p));
    return a;
}

#define CP_ASYNC16(dst, src) \
    asm volatile("cp.async.cg.shared.global [%0], [%1], 16;" :: "r"(dst), "l"(src) : "memory")
#define CP_COMMIT() asm volatile("cp.async.commit_group;" ::: "memory")
#define CP_WAIT(n)  asm volatile("cp.async.wait_group %0;" :: "n"(n) : "memory")

__device__ __forceinline__ void ldmx4(uint32_t* r, uint32_t addr) {
    asm volatile("ldmatrix.sync.aligned.m8n8.x4.shared.b16 {%0,%1,%2,%3}, [%4];"
                 : "=r"(r[0]), "=r"(r[1]), "=r"(r[2]), "=r"(r[3]) : "r"(addr));
}

__device__ __forceinline__ void mma_bf16(float* c, const uint32_t* a, const uint32_t* b) {
    asm volatile(
        "mma.sync.aligned.m16n8k16.row.col.f32.bf16.bf16.f32 "
        "{%0,%1,%2,%3}, {%4,%5,%6,%7}, {%8,%9}, {%0,%1,%2,%3};"
        : "+f"(c[0]), "+f"(c[1]), "+f"(c[2]), "+f"(c[3])
        : "r"(a[0]), "r"(a[1]), "r"(a[2]), "r"(a[3]), "r"(b[0]), "r"(b[1]));
}

// ---------------------------------------------------------------------------
// Kernel 1: warp-per-row L2-normalize + bf16 convert. Also resets g_done.
// grid=(N/8, 2), block=256 (8 warps).
// ---------------------------------------------------------------------------
__global__ __launch_bounds__(256)
void k_norm_cvt(const float* __restrict__ f1, const float* __restrict__ f2) {
    if (blockIdx.x == 0 && blockIdx.y == 0 && threadIdx.x == 0) g_done = 0;

    const int wid = threadIdx.x >> 5;
    const int lane = threadIdx.x & 31;
    const int row = blockIdx.x * 8 + wid;
    const float* __restrict__ src = (blockIdx.y == 0) ? f1 : f2;
    __nv_bfloat16* __restrict__ dst = (blockIdx.y == 0) ? g_a : g_b;

    const float4* p4 = (const float4*)(src + (size_t)row * D);
    float4 v[6];
    float s = 0.0f;
    #pragma unroll
    for (int i = 0; i < 6; i++) {          // 768/4 = 192 float4; 6 per lane
        v[i] = p4[lane + i * 32];
        s += v[i].x * v[i].x + v[i].y * v[i].y + v[i].z * v[i].z + v[i].w * v[i].w;
    }
    #pragma unroll
    for (int off = 16; off > 0; off >>= 1) s += __shfl_xor_sync(0xFFFFFFFFu, s, off);
    const float inv = 1.0f / fmaxf(sqrtf(s), EPSN);

    __nv_bfloat162* q2 = (__nv_bfloat162*)(dst + (size_t)row * D);
    #pragma unroll
    for (int i = 0; i < 6; i++) {
        const int base = (lane + i * 32) * 2;  // bf162 index
        q2[base + 0] = __floats2bfloat162_rn(v[i].x * inv, v[i].y * inv);
        q2[base + 1] = __floats2bfloat162_rn(v[i].z * inv, v[i].w * inv);
    }
}

// ---------------------------------------------------------------------------
// Kernel 2: bf16 mma.sync GEMM with fused exp-sum epilogue.
// CTA: 128x128 tile, 8 warps (2x4), each warp 64x32. BK=64, 3-stage cp.async.
// Smem rows: 128B (8 x 16B chunks), XOR-8 swizzle.
// ---------------------------------------------------------------------------
__global__ __launch_bounds__(256)
void k_gemm_fused() {
    extern __shared__ char smem[];
    const uint32_t sbase = smem_u32(smem);
    const int tid = threadIdx.x;
    const int wid = tid >> 5;
    const int lane = tid & 31;
    const int bx = blockIdx.x, by = blockIdx.y;
    const int bi = by * 128, bj = bx * 128;

    const int wy = wid >> 2;
    const int wx = wid & 3;
    const int m0 = wy * 64;
    const int n0 = wx * 32;

    // stage chunk c (k0=c*64) into stage s: 128 rows x 128B x 2 mats = 2048 x 16B
    auto load_chunk = [&](int c, int s) {
        const int k0 = c * BK;
        const uint32_t st = sbase + s * STAGE_BYTES;
        #pragma unroll
        for (int i = 0; i < 8; i++) {
            const int idx = tid + i * 256;          // 0..2047
            const int isB = idx >> 10;              // 0: A, 1: B
            const int id2 = idx & 1023;
            const int row = id2 >> 3;               // 0..127
            const int ch  = id2 & 7;                // 16B chunk in 128B row
            const uint32_t soff = (uint32_t)(row * 128 + ((ch ^ (row & 7)) << 4));
            const __nv_bfloat16* src = (isB ? g_b + (size_t)(bj + row) * D
                                            : g_a + (size_t)(bi + row) * D) + k0 + ch * 8;
            CP_ASYNC16(st + isB * 16384 + soff, src);
        }
        CP_COMMIT();
    };

    // ldmatrix lane-address precompute
    uint32_t aRB[4], aR7[4];
    #pragma unroll
    for (int mt = 0; mt < 4; mt++) {
        const int r = m0 + mt * 16 + (lane & 15);
        aRB[mt] = (uint32_t)(r * 128);
        aR7[mt] = (uint32_t)(r & 7);
    }
    uint32_t bRB[2], bR7[2];
    #pragma unroll
    for (int p = 0; p < 2; p++) {
        const int r = n0 + p * 16 + ((lane >> 4) << 3) + (lane & 7);
        bRB[p] = (uint32_t)(r * 128);
        bR7[p] = (uint32_t)(r & 7);
    }
    const uint32_t chA = (uint32_t)(lane >> 4);
    const uint32_t chB = (uint32_t)((lane >> 3) & 1);

    float acc[4][4][4];
    #pragma unroll
    for (int mt = 0; mt < 4; mt++)
        #pragma unroll
        for (int nt = 0; nt < 4; nt++)
            #pragma unroll
            for (int r = 0; r < 4; r++) acc[mt][nt][r] = 0.0f;

    load_chunk(0, 0);
    load_chunk(1, 1);

    for (int c = 0; c < NCH; c++) {
        CP_WAIT(1);
        __syncthreads();
        if (c + 2 < NCH) {
            load_chunk(c + 2, (c + 2) % 3);
        } else {
            CP_COMMIT();
        }

        const uint32_t sA = sbase + (c % 3) * STAGE_BYTES;
        const uint32_t sB = sA + 16384;

        #pragma unroll
        for (int ks = 0; ks < 4; ks++) {
            uint32_t a[4][4];
            #pragma unroll
            for (int mt = 0; mt < 4; mt++) {
                const uint32_t ch = 2 * ks + chA;
                ldmx4(a[mt], sA + aRB[mt] + ((ch ^ aR7[mt]) << 4));
            }
            uint32_t b[4][2];
            #pragma unroll
            for (int p = 0; p < 2; p++) {
                uint32_t t[4];
                const uint32_t ch = 2 * ks + chB;
                ldmx4(t, sB + bRB[p] + ((ch ^ bR7[p]) << 4));
                b[2 * p][0] = t[0]; b[2 * p][1] = t[1];
                b[2 * p + 1][0] = t[2]; b[2 * p + 1][1] = t[3];
            }
            #pragma unroll
            for (int mt = 0; mt < 4; mt++)
                #pragma unroll
                for (int nt = 0; nt < 4; nt++)
                    mma_bf16(acc[mt][nt], a[mt], b[nt]);
        }
    }

    // ---------------- fused epilogue ----------------
    const int g = lane >> 2;
    const int tig = lane & 3;
    const bool diagBlk = (bx == by);

    float rowsum[8];
    #pragma unroll
    for (int h = 0; h < 8; h++) rowsum[h] = 0.0f;

    #pragma unroll
    for (int mt = 0; mt < 4; mt++) {
        #pragma unroll
        for (int nt = 0; nt < 4; nt++) {
            const float v0 = acc[mt][nt][0] * TEMP_INV;
            const float v1 = acc[mt][nt][1] * TEMP_INV;
            const float v2 = acc[mt][nt][2] * TEMP_INV;
            const float v3 = acc[mt][nt][3] * TEMP_INV;
            rowsum[mt * 2 + 0] += __expf(v0 - 20.0f) + __expf(v1 - 20.0f);
            rowsum[mt * 2 + 1] += __expf(v2 - 20.0f) + __expf(v3 - 20.0f);
            if (diagBlk) {
                const int i0 = m0 + mt * 16 + g;
                const int i1 = i0 + 8;
                const int j0 = n0 + nt * 8 + tig * 2;
                if (i0 == j0)     g_diag[bi + i0] = v0;
                if (i0 == j0 + 1) g_diag[bi + i0] = v1;
                if (i1 == j0)     g_diag[bi + i1] = v2;
                if (i1 == j0 + 1) g_diag[bi + i1] = v3;
            }
        }
    }
    #pragma unroll
    for (int h = 0; h < 8; h++) {
        rowsum[h] += __shfl_xor_sync(0xFFFFFFFFu, rowsum[h], 1);
        rowsum[h] += __shfl_xor_sync(0xFFFFFFFFu, rowsum[h], 2);
    }

    __syncthreads();
    float* part = (float*)smem;  // [128][4]
    if (tig == 0) {
        #pragma unroll
        for (int h = 0; h < 8; h++) {
            const int r = m0 + (h >> 1) * 16 + (h & 1) * 8 + g;
            part[r * 4 + wx] = rowsum[h];
        }
    }
    __syncthreads();
    if (tid < 128) {
        const float s = part[tid * 4 + 0] + part[tid * 4 + 1] +
                        part[tid * 4 + 2] + part[tid * 4 + 3];
        g_partial[(size_t)(bi + tid) * 32 + bx] = s;
    }
}

// ---------------------------------------------------------------------------
// Kernel 3: per-row loss + deterministic mean (last block reduces).
// grid = 32 blocks x 128 threads; each thread one row.
// ---------------------------------------------------------------------------
__global__ void k_rowloss_fin(float* __restrict__ out) {
    const int row = blockIdx.x * 128 + threadIdx.x;
    const float4* p = (const float4*)(g_partial + (size_t)row * 32);
    float s = 0.0f;
    #pragma unroll
    for (int i = 0; i < 8; i++) {
        float4 v = p[i];
        s += v.x + v.y + v.z + v.w;
    }
    g_rowloss[row] = logf(s) + 20.0f - g_diag[row];

    __threadfence();
    __shared__ bool isLast;
    if (threadIdx.x == 0) {
        isLast = (atomicAdd(&g_done, 1) == 31);
    }
    __syncthreads();
    if (!isLast) return;

    // last block: deterministic mean over all 4096 rows
    float t = 0.0f;
    const float4* rl = (const float4*)g_rowloss;
    #pragma unroll
    for (int i = 0; i < 8; i++) {   // 128 threads * 8 float4 = 4096
        float4 v = rl[threadIdx.x + i * 128];
        t += v.x + v.y + v.z + v.w;
    }
    __shared__ float sm[128];
    sm[threadIdx.x] = t;
    __syncthreads();
    #pragma unroll
    for (int off = 64; off > 0; off >>= 1) {
        if (threadIdx.x < off) sm[threadIdx.x] += sm[threadIdx.x + off];
        __syncthreads();
    }
    if (threadIdx.x == 0) out[0] = sm[0] / (float)N;
}

// ---------------------------------------------------------------------------
extern "C" void kernel_launch(void* const* d_in, const int* in_sizes, int n_in,
                              void* d_out, int out_size) {
    const float* f1 = (const float*)d_in[0];
    const float* f2 = (const float*)d_in[1];
    float* out = (float*)d_out;

    cudaFuncSetAttribute(k_gemm_fused, cudaFuncAttributeMaxDynamicSharedMemorySize, SMEM_DYN);

    k_norm_cvt<<<dim3(N / 8, 2), 256>>>(f1, f2);
    k_gemm_fused<<<dim3(N / 128, N / 128), 256, SMEM_DYN>>>();
    k_rowloss_fin<<<32, 128>>>(out);
}